// round 8
// baseline (speedup 1.0000x reference)
#include <cuda_runtime.h>
#include <cuda_bf16.h>
#include <cstdint>

#define BB 16
#define NPTS 4096

// ---------------- scratch (static device globals; no allocation) ----------------
__device__ __align__(16) float g_xyz1[BB * NPTS * 3];
__device__ __align__(16) float g_feat1[BB * 6 * NPTS];
__device__ __align__(16) int   g_sidx1[BB * 512];
__device__ __align__(16) float g_xyz2[BB * 512 * 3];
__device__ __align__(16) float g_grp1[BB * 9 * 512 * 32];
__device__ __align__(16) uint32_t g_h1[BB * 64 * 512 * 32];   // packed (bf16hi|bf16lo)
__device__ __align__(16) float g_feat2[BB * 128 * 512];
__device__ __align__(16) int   g_sidx2[BB * 64];
__device__ __align__(16) float g_xyz3[BB * 64 * 3];
__device__ __align__(16) float g_grp2[BB * 131 * 64 * 64];
__device__ __align__(16) uint32_t g_h2[BB * 128 * 64 * 64];   // packed
__device__ __align__(16) float g_feat3[BB * 256 * 64];
__device__ __align__(16) int   g_sidx3[BB * 1];
__device__ __align__(16) float g_xyz4[BB * 3];
__device__ __align__(16) float g_grp3[BB * 259 * 64];
__device__ __align__(16) uint32_t g_h3[BB * 512 * 64];        // packed
__device__ __align__(16) float g_feat4[BB * 1024];
__device__ __align__(16) float g_c1[BB * 1024];
__device__ __align__(16) float g_c2[BB * 512];
__device__ __align__(16) float g_c3[BB * 128];
// bf16 hi/lo weight planes, [Cout][Cpad] row-major, Cpad = ceil(Cin/16)*16
__device__ __align__(16) __nv_bfloat16 g_wh[722944];
__device__ __align__(16) __nv_bfloat16 g_wl[722944];
#define WO0 0        // SA1-L2: 128 x 64
#define WO1 8192     // SA2-L1: 128 x 144
#define WO2 26624    // SA2-L2: 256 x 128
#define WO3 59392    // SA3-L1: 512 x 272
#define WO4 198656   // SA3-L2: 1024 x 512

// ---------------- helpers ----------------
__device__ __forceinline__ uint32_t smem_u32(const void* p) {
    return (uint32_t)__cvta_generic_to_shared(p);
}
__device__ __forceinline__ void cp16(uint32_t dst, const void* src) {
    asm volatile("cp.async.ca.shared.global [%0], [%1], 16;" :: "r"(dst), "l"(src));
}
__device__ __forceinline__ void cp_commit() {
    asm volatile("cp.async.commit_group;");
}
template <int N>
__device__ __forceinline__ void cp_wait() {
    asm volatile("cp.async.wait_group %0;" :: "n"(N));
}
__device__ __forceinline__ void mma16816(float* c, const uint32_t* a, const uint32_t* b) {
    asm("mma.sync.aligned.m16n8k16.row.col.f32.bf16.bf16.f32 "
        "{%0,%1,%2,%3},{%4,%5,%6,%7},{%8,%9},{%0,%1,%2,%3};"
        : "+f"(c[0]), "+f"(c[1]), "+f"(c[2]), "+f"(c[3])
        : "r"(a[0]), "r"(a[1]), "r"(a[2]), "r"(a[3]), "r"(b[0]), "r"(b[1]));
}
// pack f32 -> u32 (low16 = bf16 hi, high16 = bf16 of residual)
__device__ __forceinline__ uint32_t pack_hl(float v) {
    __nv_bfloat16 h = __float2bfloat16(v);
    float lo = v - __bfloat162float(h);
    return (uint32_t)__bfloat16_as_ushort(h) |
           ((uint32_t)__bfloat16_as_ushort(__float2bfloat16(lo)) << 16);
}

// ---------------- weight prep: f32 -> bf16 hi/lo planes, padded ----------------
__global__ void prep_w_kernel(const float* __restrict__ w0, const float* __restrict__ w1,
                              const float* __restrict__ w2, const float* __restrict__ w3,
                              const float* __restrict__ w4) {
    int i = blockIdx.x * 256 + threadIdx.x;
    const float* W;
    int Cin, Cpad;
    size_t off;
    if (i < 8192)        { W = w0; Cin = 64;  Cpad = 64;  off = WO0; }
    else if (i < 26624)  { W = w1; Cin = 131; Cpad = 144; off = WO1; i -= 8192; }
    else if (i < 59392)  { W = w2; Cin = 128; Cpad = 128; off = WO2; i -= 26624; }
    else if (i < 198656) { W = w3; Cin = 259; Cpad = 272; off = WO3; i -= 59392; }
    else if (i < 722944) { W = w4; Cin = 512; Cpad = 512; off = WO4; i -= 198656; }
    else return;
    int o = i / Cpad, c = i - o * Cpad;
    float v = (c < Cin) ? W[(size_t)o * Cin + c] : 0.f;
    __nv_bfloat16 h = __float2bfloat16(v);
    float lo = v - __bfloat162float(h);
    g_wh[off + i] = h;
    g_wl[off + i] = __float2bfloat16(lo);
}

// ---------------- split pointcloud ----------------
__global__ void split_kernel(const float* __restrict__ pc,
                             float* __restrict__ xyz, float* __restrict__ feat) {
    int idx = blockIdx.x * blockDim.x + threadIdx.x;
    if (idx >= BB * NPTS) return;
    int b = idx / NPTS, n = idx % NPTS;
    const float* p = pc + (size_t)idx * 9;
    xyz[idx * 3 + 0] = p[0];
    xyz[idx * 3 + 1] = p[1];
    xyz[idx * 3 + 2] = p[2];
#pragma unroll
    for (int c = 0; c < 6; c++)
        feat[((size_t)b * 6 + c) * NPTS + n] = p[3 + c];
}

// ---------------- FPS: single barrier/iter, parity-buffered reduction ----------
// Exact JAX arithmetic; argmax tie-break = smallest index.
__global__ void fps_kernel(const float* __restrict__ xyz, int N, int npoint,
                           int* __restrict__ out) {
    const int b = blockIdx.x;
    const float* px = xyz + (size_t)b * N * 3;
    const int tid = threadIdx.x;
    const int lane = tid & 31, w = tid >> 5;
    const int ITEMS = 4;

    float lx[ITEMS], ly[ITEMS], lz[ITEMS], ld[ITEMS];
#pragma unroll
    for (int i = 0; i < ITEMS; i++) {
        int n = tid + i * 1024;
        if (n < N) {
            lx[i] = px[n * 3 + 0];
            ly[i] = px[n * 3 + 1];
            lz[i] = px[n * 3 + 2];
            ld[i] = 1e10f;
        } else {
            ld[i] = -1.0f;
        }
    }

    __shared__ unsigned sv[2][32];
    __shared__ unsigned si[2][32];

    int far = 0;
    for (int it = 0; it < npoint; it++) {
        if (it > 0) {
            // reduce the 32 per-warp results written last epoch (buffer (it-1)&1)
            int buf = (it - 1) & 1;
            unsigned v2 = sv[buf][lane], i2 = si[buf][lane];
            unsigned m2 = __reduce_max_sync(0xffffffffu, v2);
            unsigned ii = (v2 == m2) ? i2 : 0xffffffffu;
            far = (int)__reduce_min_sync(0xffffffffu, ii);
        }
        if (tid == 0) out[b * npoint + it] = far;
        float cx = px[far * 3 + 0];
        float cy = px[far * 3 + 1];
        float cz = px[far * 3 + 2];

        float bv = -1.0f;
        int bi = 0;
#pragma unroll
        for (int i = 0; i < ITEMS; i++) {
            int n = tid + i * 1024;
            if (n < N) {
                float dx = __fsub_rn(lx[i], cx);
                float dy = __fsub_rn(ly[i], cy);
                float dz = __fsub_rn(lz[i], cz);
                float d = __fadd_rn(__fadd_rn(__fmul_rn(dx, dx), __fmul_rn(dy, dy)),
                                    __fmul_rn(dz, dz));
                float nd = fminf(ld[i], d);
                ld[i] = nd;
                if (nd > bv) { bv = nd; bi = n; }  // ascending n -> first-max kept
            }
        }
        // dists nonneg -> float bits order-preserving
        unsigned ub = (tid < N) ? __float_as_uint(bv) : 0u;
        unsigned wmax = __reduce_max_sync(0xffffffffu, ub);
        unsigned uidx = (tid < N && ub == wmax) ? (unsigned)bi : 0xffffffffu;
        unsigned wimin = __reduce_min_sync(0xffffffffu, uidx);
        if (lane == 0) { sv[it & 1][w] = wmax; si[it & 1][w] = wimin; }
        __syncthreads();
    }
}

// ---------------- ball query + gather/group: block-parallel scan (round-7) --------
__global__ void bq_group_kernel(const float* __restrict__ xyz, const int* __restrict__ sidx,
                                const float* __restrict__ feats,
                                float* __restrict__ new_xyz, float* __restrict__ grp,
                                int N, int S, int K, int Cf, float r2) {
    const int b = blockIdx.y, s = blockIdx.x;
    const float* px = xyz + (size_t)b * N * 3;
    const int ci = sidx[b * S + s];
    const float cx = px[ci * 3 + 0];
    const float cy = px[ci * 3 + 1];
    const float cz = px[ci * 3 + 2];
    const int tid = threadIdx.x;
    const int w = tid >> 5, l = tid & 31;

    __shared__ unsigned smask[128];
    __shared__ int sbase[128];
    __shared__ int s_total;
    __shared__ int sIdx[64];

    const int NG = (N + 31) >> 5;
    const int gpw = (NG + 7) >> 3;

    if (tid == 0) {
        new_xyz[((size_t)b * S + s) * 3 + 0] = cx;
        new_xyz[((size_t)b * S + s) * 3 + 1] = cy;
        new_xyz[((size_t)b * S + s) * 3 + 2] = cz;
    }

    for (int gi = 0; gi < gpw; gi++) {
        int g = w * gpw + gi;
        if (g < NG) {
            int j = (g << 5) + l;
            bool pred = false;
            if (j < N) {
                float dx = __fsub_rn(cx, px[j * 3 + 0]);
                float dy = __fsub_rn(cy, px[j * 3 + 1]);
                float dz = __fsub_rn(cz, px[j * 3 + 2]);
                float d2 = __fadd_rn(__fadd_rn(__fmul_rn(dx, dx), __fmul_rn(dy, dy)),
                                     __fmul_rn(dz, dz));
                pred = (d2 < r2);
            }
            unsigned m = __ballot_sync(0xffffffffu, pred);
            if (l == 0) smask[g] = m;
        }
    }
    __syncthreads();

    if (w == 0) {
        const int gpl = (NG + 31) >> 5;
        int cnt = 0;
#pragma unroll 4
        for (int q = 0; q < gpl; q++) {
            int g = l * gpl + q;
            if (g < NG) cnt += __popc(smask[g]);
        }
        int inc = cnt;
#pragma unroll
        for (int off = 1; off < 32; off <<= 1) {
            int v = __shfl_up_sync(0xffffffffu, inc, off);
            if (l >= off) inc += v;
        }
        int total = __shfl_sync(0xffffffffu, inc, 31);
        int run = inc - cnt;
#pragma unroll 4
        for (int q = 0; q < gpl; q++) {
            int g = l * gpl + q;
            if (g < NG) {
                sbase[g] = run;
                run += __popc(smask[g]);
            }
        }
        if (l == 0) s_total = total;
    }
    __syncthreads();

    const int total = s_total;
    for (int gi = 0; gi < gpw; gi++) {
        int g = w * gpw + gi;
        if (g < NG) {
            unsigned m = smask[g];
            int base = sbase[g];
            if (m != 0u && base < K) {
                if (m & (1u << l)) {
                    int pos = base + __popc(m & ((1u << l) - 1u));
                    if (pos < K) sIdx[pos] = (g << 5) + l;
                }
            }
        }
    }
    __syncthreads();
    const int fillv = (total > 0) ? sIdx[0] : 0;
    for (int k = total + tid; k < K; k += 256) sIdx[k] = fillv;
    __syncthreads();

    const int C = 3 + Cf;
    const size_t SK = (size_t)S * K;
    const size_t pbase = (size_t)s * K;
    for (int e = tid; e < C * K; e += blockDim.x) {
        int ch = e / K, k = e - ch * K;
        int j = sIdx[k];
        float v;
        if (ch == 0)      v = __fsub_rn(px[j * 3 + 0], cx);
        else if (ch == 1) v = __fsub_rn(px[j * 3 + 1], cy);
        else if (ch == 2) v = __fsub_rn(px[j * 3 + 2], cz);
        else              v = feats[((size_t)b * Cf + (ch - 3)) * N + j];
        grp[((size_t)b * C + ch) * SK + pbase + k] = v;
    }
}

// ---------------- SA1 layer1: 9 -> 64 conv + BN + ReLU, packed-bf16 output ---------
__global__ void conv9_kernel(const float* __restrict__ x, const float* __restrict__ W,
                             const float* __restrict__ g, const float* __restrict__ bi,
                             uint32_t* __restrict__ out, int P) {
    __shared__ float ws[64 * 9];
    __shared__ float gs[64], bs[64];
    const int tid = threadIdx.x;
    if (tid < 64) { gs[tid] = g[tid]; bs[tid] = bi[tid]; }
    for (int e = tid; e < 576; e += 256) ws[e] = W[e];
    __syncthreads();

    const int b = blockIdx.y;
    const int p = blockIdx.x * 256 + tid;
    const float* xb = x + (size_t)b * 9 * P;
    float xv[9];
#pragma unroll
    for (int c = 0; c < 9; c++) xv[c] = xb[(size_t)c * P + p];
    uint32_t* ob = out + (size_t)b * 64 * P;
#pragma unroll 8
    for (int o = 0; o < 64; o++) {
        float a = 0.f;
#pragma unroll
        for (int c = 0; c < 9; c++) a = fmaf(ws[o * 9 + c], xv[c], a);
        ob[(size_t)o * P + p] = pack_hl(fmaxf(fmaf(a, gs[o], bs[o]), 0.f));
    }
}

// ---------------- bf16 split-MMA GEMM: 64o x 128p block tile, K-chunk 16 -----------
// INPACK: X already stored as u32 (bf16hi | bf16lo) -> PRMT recombine, no cvt.
// OUTPACK (MAXPOOL=0 only): store packed u32 instead of f32.
template <int MAXPOOL, int INPACK, int OUTPACK>
__global__ __launch_bounds__(256, 2) void mma_gemm_kernel(
    const float* __restrict__ x, const __nv_bfloat16* __restrict__ Wh,
    const __nv_bfloat16* __restrict__ Wl, const float* __restrict__ g,
    const float* __restrict__ bi, float* __restrict__ out,
    int Cin, int Cpad, int Cout, int P, int S, int K) {
    __shared__ uint32_t sWh[2][64][12], sWl[2][64][12];
    __shared__ uint32_t sXh[128][12], sXl[128][12];
    __shared__ float red[4][64];

    const int b = blockIdx.z;
    const int o0 = blockIdx.y * 64;
    const int p0 = blockIdx.x * 128;
    const int tid = threadIdx.x;
    const int w = tid >> 5, l = tid & 31;
    const int gq = l >> 2, tq = l & 3;
    const int wm = w & 1, wn = w >> 1;

    const float* xb = x + (size_t)b * Cin * P;
    const uint32_t* xbp = (const uint32_t*)xb;
    const int nch = (Cin + 15) >> 4;

    float acc[2][4][4];
#pragma unroll
    for (int i = 0; i < 2; i++)
#pragma unroll
        for (int j = 0; j < 4; j++)
#pragma unroll
            for (int r = 0; r < 4; r++) acc[i][j][r] = 0.f;

    auto stage_w = [&](int c0, int buf) {
        int which = tid & 1, r = (tid >> 1) & 63, half = (tid >> 7) & 1;
        const __nv_bfloat16* src =
            (which ? Wl : Wh) + (size_t)(o0 + r) * Cpad + c0 + half * 8;
        uint32_t dst = smem_u32(which ? &sWl[buf][r][half * 4] : &sWh[buf][r][half * 4]);
        cp16(dst, src);
    };
    const int xp = tid & 127;
    const int xch = (tid >> 7) * 8;

    float xrf[8], xrf2[8];
    uint32_t xru[8], xru2[8];

    auto load_x = [&](int c0, float xf[8], uint32_t xu[8]) {
        bool pv = (p0 + xp) < P;
#pragma unroll
        for (int q = 0; q < 8; q++) {
            int cc = c0 + xch + q;
            bool v = pv && (cc < Cin);
            if (INPACK)
                xu[q] = v ? xbp[(size_t)cc * P + p0 + xp] : 0u;
            else
                xf[q] = v ? xb[(size_t)cc * P + p0 + xp] : 0.f;
        }
    };
    auto store_x = [&](const float xf[8], const uint32_t xu[8]) {
        uint32_t hq[4], lq[4];
#pragma unroll
        for (int k = 0; k < 4; k++) {
            if (INPACK) {
                uint32_t a = xu[2 * k], c = xu[2 * k + 1];
                hq[k] = __byte_perm(a, c, 0x5410);  // low halves  (hi plane)
                lq[k] = __byte_perm(a, c, 0x7632);  // high halves (lo plane)
            } else {
                float a = xf[2 * k], c = xf[2 * k + 1];
                __nv_bfloat16 ah = __float2bfloat16(a), ch = __float2bfloat16(c);
                float al = a - __bfloat162float(ah), cl = c - __bfloat162float(ch);
                hq[k] = (uint32_t)__bfloat16_as_ushort(ah) |
                        ((uint32_t)__bfloat16_as_ushort(ch) << 16);
                lq[k] = (uint32_t)__bfloat16_as_ushort(__float2bfloat16(al)) |
                        ((uint32_t)__bfloat16_as_ushort(__float2bfloat16(cl)) << 16);
            }
        }
        *(uint4*)&sXh[xp][(xch >> 1)] = make_uint4(hq[0], hq[1], hq[2], hq[3]);
        *(uint4*)&sXl[xp][(xch >> 1)] = make_uint4(lq[0], lq[1], lq[2], lq[3]);
    };

    load_x(0, xrf, xru);
    stage_w(0, 0);
    cp_commit();

    for (int c = 0; c < nch; c++) {
        __syncthreads();
        store_x(xrf, xru);
        if (c + 1 < nch) {
            load_x((c + 1) * 16, xrf2, xru2);
            stage_w((c + 1) * 16, (c + 1) & 1);
            cp_commit();
            cp_wait<1>();
        } else {
            cp_wait<0>();
        }
        __syncthreads();

        const uint32_t(*wh)[12] = sWh[c & 1];
        const uint32_t(*wl)[12] = sWl[c & 1];
        uint32_t ah[2][4], al[2][4], bh[4][2], bl[4][2];
#pragma unroll
        for (int i = 0; i < 2; i++) {
            int ro = wm * 32 + i * 16;
            ah[i][0] = wh[ro + gq][tq];
            ah[i][1] = wh[ro + gq + 8][tq];
            ah[i][2] = wh[ro + gq][tq + 4];
            ah[i][3] = wh[ro + gq + 8][tq + 4];
            al[i][0] = wl[ro + gq][tq];
            al[i][1] = wl[ro + gq + 8][tq];
            al[i][2] = wl[ro + gq][tq + 4];
            al[i][3] = wl[ro + gq + 8][tq + 4];
        }
#pragma unroll
        for (int j = 0; j < 4; j++) {
            int rp = wn * 32 + j * 8 + gq;
            bh[j][0] = sXh[rp][tq];
            bh[j][1] = sXh[rp][tq + 4];
            bl[j][0] = sXl[rp][tq];
            bl[j][1] = sXl[rp][tq + 4];
        }
#pragma unroll
        for (int i = 0; i < 2; i++)
#pragma unroll
            for (int j = 0; j < 4; j++) {
                mma16816(acc[i][j], ah[i], bh[j]);
                mma16816(acc[i][j], ah[i], bl[j]);
                mma16816(acc[i][j], al[i], bh[j]);
            }
        if (c + 1 < nch) {
#pragma unroll
            for (int q = 0; q < 8; q++) {
                xrf[q] = xrf2[q];
                xru[q] = xru2[q];
            }
        }
    }

#pragma unroll
    for (int i = 0; i < 2; i++) {
#pragma unroll
        for (int half = 0; half < 2; half++) {
            int orow = o0 + wm * 32 + i * 16 + gq + half * 8;
            float gv = g[orow], bv = bi[orow];
            if (MAXPOOL == 0) {
#pragma unroll
                for (int j = 0; j < 4; j++) {
                    int pb = p0 + wn * 32 + j * 8 + 2 * tq;
                    float v0 = fmaxf(fmaf(acc[i][j][half * 2], gv, bv), 0.f);
                    float v1 = fmaxf(fmaf(acc[i][j][half * 2 + 1], gv, bv), 0.f);
                    if (OUTPACK) {
                        uint32_t* ob =
                            (uint32_t*)out + (size_t)b * Cout * P + (size_t)orow * P;
                        if (pb < P) ob[pb] = pack_hl(v0);
                        if (pb + 1 < P) ob[pb + 1] = pack_hl(v1);
                    } else {
                        float* ob = out + (size_t)b * Cout * P + (size_t)orow * P;
                        if (pb < P) ob[pb] = v0;
                        if (pb + 1 < P) ob[pb + 1] = v1;
                    }
                }
            } else {
                float m = 0.f;
#pragma unroll
                for (int j = 0; j < 4; j++) {
                    m = fmaxf(m, fmaxf(fmaf(acc[i][j][half * 2], gv, bv),
                                       fmaf(acc[i][j][half * 2 + 1], gv, bv)));
                }
                m = fmaxf(m, 0.f);
                m = fmaxf(m, __shfl_xor_sync(0xffffffffu, m, 1));
                m = fmaxf(m, __shfl_xor_sync(0xffffffffu, m, 2));
                if (tq == 0) red[wn][wm * 32 + i * 16 + half * 8 + gq] = m;
            }
        }
    }
    if (MAXPOOL == 1) {
        __syncthreads();
        if (K == 32) {
            int o = tid & 63, grp = tid >> 6;
            if (p0 + grp * 32 < P)
                out[((size_t)b * Cout + o0 + o) * S + (p0 >> 5) + grp] = red[grp][o];
        } else {
            if (tid < 128) {
                int o = tid & 63, grp = tid >> 6;
                if (p0 + grp * 64 < P) {
                    float m = fmaxf(red[2 * grp][o], red[2 * grp + 1][o]);
                    out[((size_t)b * Cout + o0 + o) * S + (p0 >> 6) + grp] = m;
                }
            }
        }
    }
}

// ---------------- dense layer on [B, Cin] vectors (classifier head) ----------------
__global__ void dense_kernel(const float* __restrict__ x, const float* __restrict__ W,
                             const float* __restrict__ g, const float* __restrict__ bi,
                             float* __restrict__ out, int Cin, int Cout, int do_relu) {
    const int b = blockIdx.x;
    const int o = blockIdx.y * 8 + (threadIdx.x >> 5);
    const int lane = threadIdx.x & 31;
    if (o >= Cout) return;
    const float* xb = x + (size_t)b * Cin;
    float acc = 0.f;
    for (int c = lane; c < Cin; c += 32)
        acc = fmaf(W[(size_t)o * Cin + c], xb[c], acc);
#pragma unroll
    for (int off = 16; off; off >>= 1)
        acc += __shfl_xor_sync(0xffffffffu, acc, off);
    if (lane == 0) {
        float v = g ? fmaf(acc, g[o], bi[o]) : (acc + bi[o]);
        if (do_relu) v = fmaxf(v, 0.f);
        out[(size_t)b * Cout + o] = v;
    }
}

// ---------------- launch ----------------
extern "C" void kernel_launch(void* const* d_in, const int* in_sizes, int n_in,
                              void* d_out, int out_size) {
    const float* pc = (const float*)d_in[0];
    const float* saw[3][2];
    const float* sag[3][2];
    const float* sab[3][2];
    for (int sm = 0; sm < 3; sm++)
        for (int l = 0; l < 2; l++) {
            int base = 1 + sm * 6 + l * 3;
            saw[sm][l] = (const float*)d_in[base + 0];
            sag[sm][l] = (const float*)d_in[base + 1];
            sab[sm][l] = (const float*)d_in[base + 2];
        }
    const float* clsw[4];
    const float* clsg[3];
    const float* clsb[4];
    for (int l = 0; l < 3; l++) {
        clsw[l] = (const float*)d_in[19 + l * 3 + 0];
        clsg[l] = (const float*)d_in[19 + l * 3 + 1];
        clsb[l] = (const float*)d_in[19 + l * 3 + 2];
    }
    clsw[3] = (const float*)d_in[28];
    clsb[3] = (const float*)d_in[29];

    float *xyz1, *feat1, *xyz2, *grp1, *feat2, *xyz3, *grp2, *feat3;
    float *xyz4, *grp3, *feat4, *c1, *c2, *c3;
    uint32_t *h1, *h2, *h3;
    int *sidx1, *sidx2, *sidx3;
    __nv_bfloat16 *wh, *wl;
    cudaGetSymbolAddress((void**)&xyz1, g_xyz1);
    cudaGetSymbolAddress((void**)&feat1, g_feat1);
    cudaGetSymbolAddress((void**)&sidx1, g_sidx1);
    cudaGetSymbolAddress((void**)&xyz2, g_xyz2);
    cudaGetSymbolAddress((void**)&grp1, g_grp1);
    cudaGetSymbolAddress((void**)&h1, g_h1);
    cudaGetSymbolAddress((void**)&feat2, g_feat2);
    cudaGetSymbolAddress((void**)&sidx2, g_sidx2);
    cudaGetSymbolAddress((void**)&xyz3, g_xyz3);
    cudaGetSymbolAddress((void**)&grp2, g_grp2);
    cudaGetSymbolAddress((void**)&h2, g_h2);
    cudaGetSymbolAddress((void**)&feat3, g_feat3);
    cudaGetSymbolAddress((void**)&sidx3, g_sidx3);
    cudaGetSymbolAddress((void**)&xyz4, g_xyz4);
    cudaGetSymbolAddress((void**)&grp3, g_grp3);
    cudaGetSymbolAddress((void**)&h3, g_h3);
    cudaGetSymbolAddress((void**)&feat4, g_feat4);
    cudaGetSymbolAddress((void**)&c1, g_c1);
    cudaGetSymbolAddress((void**)&c2, g_c2);
    cudaGetSymbolAddress((void**)&c3, g_c3);
    cudaGetSymbolAddress((void**)&wh, g_wh);
    cudaGetSymbolAddress((void**)&wl, g_wl);

    prep_w_kernel<<<(722944 + 255) / 256, 256>>>(saw[0][1], saw[1][0], saw[1][1],
                                                 saw[2][0], saw[2][1]);
    split_kernel<<<(BB * NPTS + 255) / 256, 256>>>(pc, xyz1, feat1);

    // ---- SA1: N=4096 -> S=512, K=32, r=0.1, C: 9 -> 64 -> 128 ----
    fps_kernel<<<BB, 1024>>>(xyz1, NPTS, 512, sidx1);
    bq_group_kernel<<<dim3(512, BB), 256>>>(xyz1, sidx1, feat1, xyz2, grp1,
                                            NPTS, 512, 32, 6, (float)(0.1 * 0.1));
    conv9_kernel<<<dim3(16384 / 256, BB), 256>>>(
        grp1, saw[0][0], sag[0][0], sab[0][0], h1, 16384);
    mma_gemm_kernel<1, 1, 0><<<dim3(16384 / 128, 2, BB), 256>>>(
        (const float*)h1, wh + WO0, wl + WO0, sag[0][1], sab[0][1], feat2,
        64, 64, 128, 16384, 512, 32);

    // ---- SA2: N=512 -> S=64, K=64, r=0.2, C: 131 -> 128 -> 256 ----
    fps_kernel<<<BB, 1024>>>(xyz2, 512, 64, sidx2);
    bq_group_kernel<<<dim3(64, BB), 256>>>(xyz2, sidx2, feat2, xyz3, grp2,
                                           512, 64, 64, 128, (float)(0.2 * 0.2));
    mma_gemm_kernel<0, 0, 1><<<dim3(4096 / 128, 2, BB), 256>>>(
        grp2, wh + WO1, wl + WO1, sag[1][0], sab[1][0], (float*)h2,
        131, 144, 128, 4096, 1, 1);
    mma_gemm_kernel<1, 1, 0><<<dim3(4096 / 128, 4, BB), 256>>>(
        (const float*)h2, wh + WO2, wl + WO2, sag[1][1], sab[1][1], feat3,
        128, 128, 256, 4096, 64, 64);

    // ---- SA3: N=64 -> S=1, K=64, r=0.4, C: 259 -> 512 -> 1024 ----
    fps_kernel<<<BB, 1024>>>(xyz3, 64, 1, sidx3);
    bq_group_kernel<<<dim3(1, BB), 256>>>(xyz3, sidx3, feat3, xyz4, grp3,
                                          64, 1, 64, 256, (float)(0.4 * 0.4));
    mma_gemm_kernel<0, 0, 1><<<dim3(1, 8, BB), 256>>>(
        grp3, wh + WO3, wl + WO3, sag[2][0], sab[2][0], (float*)h3,
        259, 272, 512, 64, 1, 1);
    mma_gemm_kernel<1, 1, 0><<<dim3(1, 16, BB), 256>>>(
        (const float*)h3, wh + WO4, wl + WO4, sag[2][1], sab[2][1], feat4,
        512, 512, 1024, 64, 1, 64);

    // ---- classifier head on [B, 1024] ----
    dense_kernel<<<dim3(BB, 1024 / 8), 256>>>(feat4, clsw[0], clsg[0], clsb[0], c1, 1024, 1024, 1);
    dense_kernel<<<dim3(BB, 512 / 8), 256>>>(c1, clsw[1], clsg[1], clsb[1], c2, 1024, 512, 1);
    dense_kernel<<<dim3(BB, 128 / 8), 256>>>(c2, clsw[2], clsg[2], clsb[2], c3, 512, 128, 1);
    dense_kernel<<<dim3(BB, (63 + 7) / 8), 256>>>(c3, clsw[3], nullptr, clsb[3],
                                                  (float*)d_out, 128, 63, 0);
}

// round 9
// speedup vs baseline: 1.1273x; 1.1273x over previous
#include <cuda_runtime.h>
#include <cuda_bf16.h>
#include <cstdint>

#define BB 16
#define NPTS 4096

// ---------------- scratch (static device globals; no allocation) ----------------
// xyz buffers are SoA: [B][3][N]
__device__ __align__(16) float g_xyz1[BB * 3 * NPTS];
__device__ __align__(16) float g_feat1[BB * 6 * NPTS];
__device__ __align__(16) int   g_sidx1[BB * 512];
__device__ __align__(16) float g_xyz2[BB * 3 * 512];
__device__ __align__(16) float g_grp1[BB * 9 * 512 * 32];
__device__ __align__(16) float g_h1[BB * 64 * 512 * 32];
__device__ __align__(16) float g_feat2[BB * 128 * 512];
__device__ __align__(16) int   g_sidx2[BB * 64];
__device__ __align__(16) float g_xyz3[BB * 3 * 64];
__device__ __align__(16) float g_grp2[BB * 131 * 64 * 64];
__device__ __align__(16) float g_h2[BB * 128 * 64 * 64];
__device__ __align__(16) float g_feat3[BB * 256 * 64];
__device__ __align__(16) int   g_sidx3[BB * 1];
__device__ __align__(16) float g_xyz4[BB * 3];
__device__ __align__(16) float g_grp3[BB * 259 * 64];
__device__ __align__(16) float g_h3[BB * 512 * 64];
__device__ __align__(16) float g_feat4[BB * 1024];
__device__ __align__(16) float g_c1[BB * 1024];
__device__ __align__(16) float g_c2[BB * 512];
__device__ __align__(16) float g_c3[BB * 128];
// bf16 hi/lo weight planes, [Cout][Cpad] row-major, Cpad = ceil(Cin/16)*16
__device__ __align__(16) __nv_bfloat16 g_wh[722944];
__device__ __align__(16) __nv_bfloat16 g_wl[722944];
#define WO0 0        // SA1-L2: 128 x 64
#define WO1 8192     // SA2-L1: 128 x 144
#define WO2 26624    // SA2-L2: 256 x 128
#define WO3 59392    // SA3-L1: 512 x 272
#define WO4 198656   // SA3-L2: 1024 x 512

// ---------------- helpers ----------------
__device__ __forceinline__ uint32_t smem_u32(const void* p) {
    return (uint32_t)__cvta_generic_to_shared(p);
}
__device__ __forceinline__ void cp16(uint32_t dst, const void* src) {
    asm volatile("cp.async.ca.shared.global [%0], [%1], 16;" :: "r"(dst), "l"(src));
}
__device__ __forceinline__ void cp_commit() {
    asm volatile("cp.async.commit_group;");
}
template <int N>
__device__ __forceinline__ void cp_wait() {
    asm volatile("cp.async.wait_group %0;" :: "n"(N));
}
__device__ __forceinline__ void mma16816(float* c, const uint32_t* a, const uint32_t* b) {
    asm("mma.sync.aligned.m16n8k16.row.col.f32.bf16.bf16.f32 "
        "{%0,%1,%2,%3},{%4,%5,%6,%7},{%8,%9},{%0,%1,%2,%3};"
        : "+f"(c[0]), "+f"(c[1]), "+f"(c[2]), "+f"(c[3])
        : "r"(a[0]), "r"(a[1]), "r"(a[2]), "r"(a[3]), "r"(b[0]), "r"(b[1]));
}
// f32x2 packed ops (per-half IEEE rn — bitwise identical to scalar chain)
__device__ __forceinline__ unsigned long long pk2(float lo, float hi) {
    unsigned long long r;
    asm("mov.b64 %0, {%1, %2};" : "=l"(r) : "f"(lo), "f"(hi));
    return r;
}
__device__ __forceinline__ void upk2(float& lo, float& hi, unsigned long long v) {
    asm("mov.b64 {%0, %1}, %2;" : "=f"(lo), "=f"(hi) : "l"(v));
}
__device__ __forceinline__ unsigned long long add2(unsigned long long a,
                                                   unsigned long long b) {
    unsigned long long r;
    asm("add.rn.f32x2 %0, %1, %2;" : "=l"(r) : "l"(a), "l"(b));
    return r;
}
__device__ __forceinline__ unsigned long long mul2(unsigned long long a,
                                                   unsigned long long b) {
    unsigned long long r;
    asm("mul.rn.f32x2 %0, %1, %2;" : "=l"(r) : "l"(a), "l"(b));
    return r;
}

// ---------------- weight prep: f32 -> bf16 hi/lo planes, padded ----------------
__global__ void prep_w_kernel(const float* __restrict__ w0, const float* __restrict__ w1,
                              const float* __restrict__ w2, const float* __restrict__ w3,
                              const float* __restrict__ w4) {
    int i = blockIdx.x * 256 + threadIdx.x;
    const float* W;
    int Cin, Cpad;
    size_t off;
    if (i < 8192)        { W = w0; Cin = 64;  Cpad = 64;  off = WO0; }
    else if (i < 26624)  { W = w1; Cin = 131; Cpad = 144; off = WO1; i -= 8192; }
    else if (i < 59392)  { W = w2; Cin = 128; Cpad = 128; off = WO2; i -= 26624; }
    else if (i < 198656) { W = w3; Cin = 259; Cpad = 272; off = WO3; i -= 59392; }
    else if (i < 722944) { W = w4; Cin = 512; Cpad = 512; off = WO4; i -= 198656; }
    else return;
    int o = i / Cpad, c = i - o * Cpad;
    float v = (c < Cin) ? W[(size_t)o * Cin + c] : 0.f;
    __nv_bfloat16 h = __float2bfloat16(v);
    float lo = v - __bfloat162float(h);
    g_wh[off + i] = h;
    g_wl[off + i] = __float2bfloat16(lo);
}

// ---------------- split pointcloud: xyz SoA [B][3][N], feats [B][6][N] -----------
__global__ void split_kernel(const float* __restrict__ pc,
                             float* __restrict__ xyz, float* __restrict__ feat) {
    int idx = blockIdx.x * blockDim.x + threadIdx.x;
    if (idx >= BB * NPTS) return;
    int b = idx / NPTS, n = idx % NPTS;
    const float* p = pc + (size_t)idx * 9;
#pragma unroll
    for (int k = 0; k < 3; k++)
        xyz[((size_t)b * 3 + k) * NPTS + n] = p[k];
#pragma unroll
    for (int c = 0; c < 6; c++)
        feat[((size_t)b * 6 + c) * NPTS + n] = p[3 + c];
}

// ---------------- FPS: SoA input, two-level REDUX (round-7), optional f32x2 -------
// xyz: [B][3][N] SoA. PACKED requires N == 4*blockDim (no bounds checks).
template <int ITEMS, bool PACKED>
__global__ void fps_kernel(const float* __restrict__ xyz, int N, int npoint,
                           int* __restrict__ out) {
    const int b = blockIdx.x;
    const float* X = xyz + (size_t)b * 3 * N;
    const float* Y = X + N;
    const float* Z = X + 2 * N;
    const int tid = threadIdx.x;

    __shared__ int s_far;
    __shared__ unsigned sv[32];
    __shared__ unsigned si[32];
    if (tid == 0) s_far = 0;

    // packed state (pairs) or scalar state
    unsigned long long lx2[(ITEMS + 1) / 2], ly2[(ITEMS + 1) / 2],
        lz2[(ITEMS + 1) / 2], ld2[(ITEMS + 1) / 2];
    float lx[ITEMS], ly[ITEMS], lz[ITEMS], ld[ITEMS];

    if (PACKED) {
#pragma unroll
        for (int p = 0; p < ITEMS / 2; p++) {
            int n0 = tid + (2 * p) * 1024, n1 = tid + (2 * p + 1) * 1024;
            lx2[p] = pk2(X[n0], X[n1]);
            ly2[p] = pk2(Y[n0], Y[n1]);
            lz2[p] = pk2(Z[n0], Z[n1]);
            ld2[p] = pk2(1e10f, 1e10f);
        }
    } else {
#pragma unroll
        for (int i = 0; i < ITEMS; i++) {
            int n = tid + i * 1024;
            if (n < N) {
                lx[i] = X[n];
                ly[i] = Y[n];
                lz[i] = Z[n];
                ld[i] = 1e10f;
            } else {
                ld[i] = -1.0f;
            }
        }
    }
    __syncthreads();

    for (int it = 0; it < npoint; it++) {
        int far = s_far;
        if (tid == 0) out[b * npoint + it] = far;
        float cx = X[far], cy = Y[far], cz = Z[far];

        float bv = -1.0f;
        int bi = 0;
        if (PACKED) {
            unsigned long long ncx = pk2(-cx, -cx);
            unsigned long long ncy = pk2(-cy, -cy);
            unsigned long long ncz = pk2(-cz, -cz);
#pragma unroll
            for (int p = 0; p < ITEMS / 2; p++) {
                unsigned long long dx = add2(lx2[p], ncx);
                unsigned long long dy = add2(ly2[p], ncy);
                unsigned long long dz = add2(lz2[p], ncz);
                unsigned long long d =
                    add2(add2(mul2(dx, dx), mul2(dy, dy)), mul2(dz, dz));
                float d0, d1, l0, l1;
                upk2(d0, d1, d);
                upk2(l0, l1, ld2[p]);
                float n0 = fminf(l0, d0), n1 = fminf(l1, d1);
                ld2[p] = pk2(n0, n1);
                if (n0 > bv) { bv = n0; bi = tid + (2 * p) * 1024; }
                if (n1 > bv) { bv = n1; bi = tid + (2 * p + 1) * 1024; }
            }
        } else {
#pragma unroll
            for (int i = 0; i < ITEMS; i++) {
                int n = tid + i * 1024;
                if (n < N) {
                    float dx = __fsub_rn(lx[i], cx);
                    float dy = __fsub_rn(ly[i], cy);
                    float dz = __fsub_rn(lz[i], cz);
                    float d = __fadd_rn(__fadd_rn(__fmul_rn(dx, dx), __fmul_rn(dy, dy)),
                                        __fmul_rn(dz, dz));
                    float nd = fminf(ld[i], d);
                    ld[i] = nd;
                    if (nd > bv) { bv = nd; bi = n; }
                }
            }
        }
        // dists nonneg -> float bits order-preserving; tie-break = smallest index
        unsigned ub = (PACKED || tid < N) ? __float_as_uint(bv) : 0u;
        unsigned wmax = __reduce_max_sync(0xffffffffu, ub);
        unsigned uidx = ((PACKED || tid < N) && ub == wmax) ? (unsigned)bi : 0xffffffffu;
        unsigned wimin = __reduce_min_sync(0xffffffffu, uidx);
        if ((tid & 31) == 0) { sv[tid >> 5] = wmax; si[tid >> 5] = wimin; }
        __syncthreads();
        if (tid < 32) {
            unsigned v2 = sv[tid], i2 = si[tid];
            unsigned m2 = __reduce_max_sync(0xffffffffu, v2);
            unsigned ii = (v2 == m2) ? i2 : 0xffffffffu;
            unsigned fi = __reduce_min_sync(0xffffffffu, ii);
            if (tid == 0) s_far = (int)fi;
        }
        __syncthreads();
    }
}

// ---------------- ball query + gather/group: SoA xyz, templated K -----------------
// Phase A: 8 warps ballot all N points in parallel. Phase B: warp0 prefix-sum.
// Phase C: extract global rank < K; pad with rank-0 hit or 0. First-K-in-order.
template <int K>
__global__ void bq_group_kernel(const float* __restrict__ xyz, const int* __restrict__ sidx,
                                const float* __restrict__ feats,
                                float* __restrict__ new_xyz, float* __restrict__ grp,
                                int N, int S, int Cf, float r2) {
    const int b = blockIdx.y, s = blockIdx.x;
    const float* X = xyz + (size_t)b * 3 * N;
    const float* Y = X + N;
    const float* Z = X + 2 * N;
    const int ci = sidx[b * S + s];
    const float cx = X[ci], cy = Y[ci], cz = Z[ci];
    const int tid = threadIdx.x;
    const int w = tid >> 5, l = tid & 31;

    __shared__ unsigned smask[128];
    __shared__ int sbase[128];
    __shared__ int s_total;
    __shared__ int sIdx[64];

    const int NG = (N + 31) >> 5;
    const int gpw = (NG + 7) >> 3;

    if (tid == 0) {
        new_xyz[((size_t)b * 3 + 0) * S + s] = cx;
        new_xyz[((size_t)b * 3 + 1) * S + s] = cy;
        new_xyz[((size_t)b * 3 + 2) * S + s] = cz;
    }

    for (int gi = 0; gi < gpw; gi++) {
        int g = w * gpw + gi;
        if (g < NG) {
            int j = (g << 5) + l;
            bool pred = false;
            if (j < N) {
                float dx = __fsub_rn(cx, X[j]);
                float dy = __fsub_rn(cy, Y[j]);
                float dz = __fsub_rn(cz, Z[j]);
                float d2 = __fadd_rn(__fadd_rn(__fmul_rn(dx, dx), __fmul_rn(dy, dy)),
                                     __fmul_rn(dz, dz));
                pred = (d2 < r2);
            }
            unsigned m = __ballot_sync(0xffffffffu, pred);
            if (l == 0) smask[g] = m;
        }
    }
    __syncthreads();

    if (w == 0) {
        const int gpl = (NG + 31) >> 5;
        int cnt = 0;
#pragma unroll 4
        for (int q = 0; q < gpl; q++) {
            int g = l * gpl + q;
            if (g < NG) cnt += __popc(smask[g]);
        }
        int inc = cnt;
#pragma unroll
        for (int off = 1; off < 32; off <<= 1) {
            int v = __shfl_up_sync(0xffffffffu, inc, off);
            if (l >= off) inc += v;
        }
        int total = __shfl_sync(0xffffffffu, inc, 31);
        int run = inc - cnt;
#pragma unroll 4
        for (int q = 0; q < gpl; q++) {
            int g = l * gpl + q;
            if (g < NG) {
                sbase[g] = run;
                run += __popc(smask[g]);
            }
        }
        if (l == 0) s_total = total;
    }
    __syncthreads();

    const int total = s_total;
    for (int gi = 0; gi < gpw; gi++) {
        int g = w * gpw + gi;
        if (g < NG) {
            unsigned m = smask[g];
            int base = sbase[g];
            if (m != 0u && base < K) {
                if (m & (1u << l)) {
                    int pos = base + __popc(m & ((1u << l) - 1u));
                    if (pos < K) sIdx[pos] = (g << 5) + l;
                }
            }
        }
    }
    __syncthreads();
    const int fillv = (total > 0) ? sIdx[0] : 0;
    for (int k = total + tid; k < K; k += 256) sIdx[k] = fillv;
    __syncthreads();

    const int C = 3 + Cf;
    const size_t SK = (size_t)S * K;
    const size_t pbase = (size_t)s * K;
    for (int e = tid; e < C * K; e += 256) {
        int ch = e / K, k = e - ch * K;  // K compile-time -> shifts
        int j = sIdx[k];
        float v;
        if (ch == 0)      v = __fsub_rn(X[j], cx);
        else if (ch == 1) v = __fsub_rn(Y[j], cy);
        else if (ch == 2) v = __fsub_rn(Z[j], cz);
        else              v = feats[((size_t)b * Cf + (ch - 3)) * N + j];
        grp[((size_t)b * C + ch) * SK + pbase + k] = v;
    }
}

// ---------------- SA1 layer1: 9 -> 64 streaming conv + BN + ReLU ----------------
__global__ void conv9_kernel(const float* __restrict__ x, const float* __restrict__ W,
                             const float* __restrict__ g, const float* __restrict__ bi,
                             float* __restrict__ out, int P) {
    __shared__ float ws[64 * 9];
    __shared__ float gs[64], bs[64];
    const int tid = threadIdx.x;
    if (tid < 64) { gs[tid] = g[tid]; bs[tid] = bi[tid]; }
    for (int e = tid; e < 576; e += 256) ws[e] = W[e];
    __syncthreads();

    const int b = blockIdx.y;
    const int p = blockIdx.x * 256 + tid;
    const float* xb = x + (size_t)b * 9 * P;
    float xv[9];
#pragma unroll
    for (int c = 0; c < 9; c++) xv[c] = xb[(size_t)c * P + p];
    float* ob = out + (size_t)b * 64 * P;
#pragma unroll 8
    for (int o = 0; o < 64; o++) {
        float a = 0.f;
#pragma unroll
        for (int c = 0; c < 9; c++) a = fmaf(ws[o * 9 + c], xv[c], a);
        ob[(size_t)o * P + p] = fmaxf(fmaf(a, gs[o], bs[o]), 0.f);
    }
}

// ---------------- bf16 split-MMA GEMM: 64o x 128p block tile, K-chunk 16 -----------
template <int MAXPOOL>
__global__ __launch_bounds__(256, 2) void mma_gemm_kernel(
    const float* __restrict__ x, const __nv_bfloat16* __restrict__ Wh,
    const __nv_bfloat16* __restrict__ Wl, const float* __restrict__ g,
    const float* __restrict__ bi, float* __restrict__ out,
    int Cin, int Cpad, int Cout, int P, int S, int K) {
    __shared__ uint32_t sWh[2][64][12], sWl[2][64][12];
    __shared__ uint32_t sXh[128][12], sXl[128][12];
    __shared__ float red[4][64];

    const int b = blockIdx.z;
    const int o0 = blockIdx.y * 64;
    const int p0 = blockIdx.x * 128;
    const int tid = threadIdx.x;
    const int w = tid >> 5, l = tid & 31;
    const int gq = l >> 2, tq = l & 3;
    const int wm = w & 1, wn = w >> 1;

    const float* xb = x + (size_t)b * Cin * P;
    const int nch = (Cin + 15) >> 4;

    float acc[2][4][4];
#pragma unroll
    for (int i = 0; i < 2; i++)
#pragma unroll
        for (int j = 0; j < 4; j++)
#pragma unroll
            for (int r = 0; r < 4; r++) acc[i][j][r] = 0.f;

    auto stage_w = [&](int c0, int buf) {
        int which = tid & 1, r = (tid >> 1) & 63, half = (tid >> 7) & 1;
        const __nv_bfloat16* src =
            (which ? Wl : Wh) + (size_t)(o0 + r) * Cpad + c0 + half * 8;
        uint32_t dst = smem_u32(which ? &sWl[buf][r][half * 4] : &sWh[buf][r][half * 4]);
        cp16(dst, src);
    };
    const int xp = tid & 127;
    const int xch = (tid >> 7) * 8;
    auto load_x = [&](int c0, float xr[8]) {
        bool pv = (p0 + xp) < P;
#pragma unroll
        for (int q = 0; q < 8; q++) {
            int cc = c0 + xch + q;
            xr[q] = (pv && cc < Cin) ? xb[(size_t)cc * P + p0 + xp] : 0.f;
        }
    };
    auto store_x = [&](const float xr[8]) {
        uint32_t hq[4], lq[4];
#pragma unroll
        for (int k = 0; k < 4; k++) {
            float a = xr[2 * k], c = xr[2 * k + 1];
            __nv_bfloat16 ah = __float2bfloat16(a), ch = __float2bfloat16(c);
            float al = a - __bfloat162float(ah), cl = c - __bfloat162float(ch);
            hq[k] = (uint32_t)__bfloat16_as_ushort(ah) |
                    ((uint32_t)__bfloat16_as_ushort(ch) << 16);
            lq[k] = (uint32_t)__bfloat16_as_ushort(__float2bfloat16(al)) |
                    ((uint32_t)__bfloat16_as_ushort(__float2bfloat16(cl)) << 16);
        }
        *(uint4*)&sXh[xp][(xch >> 1)] = make_uint4(hq[0], hq[1], hq[2], hq[3]);
        *(uint4*)&sXl[xp][(xch >> 1)] = make_uint4(lq[0], lq[1], lq[2], lq[3]);
    };

    float xr[8], xr2[8];
    load_x(0, xr);
    stage_w(0, 0);
    cp_commit();

    for (int c = 0; c < nch; c++) {
        __syncthreads();
        store_x(xr);
        if (c + 1 < nch) {
            load_x((c + 1) * 16, xr2);
            stage_w((c + 1) * 16, (c + 1) & 1);
            cp_commit();
            cp_wait<1>();
        } else {
            cp_wait<0>();
        }
        __syncthreads();

        const uint32_t(*wh)[12] = sWh[c & 1];
        const uint32_t(*wl)[12] = sWl[c & 1];
        uint32_t ah[2][4], al[2][4], bh[4][2], bl[4][2];
#pragma unroll
        for (int i = 0; i < 2; i++) {
            int ro = wm * 32 + i * 16;
            ah[i][0] = wh[ro + gq][tq];
            ah[i][1] = wh[ro + gq + 8][tq];
            ah[i][2] = wh[ro + gq][tq + 4];
            ah[i][3] = wh[ro + gq + 8][tq + 4];
            al[i][0] = wl[ro + gq][tq];
            al[i][1] = wl[ro + gq + 8][tq];
            al[i][2] = wl[ro + gq][tq + 4];
            al[i][3] = wl[ro + gq + 8][tq + 4];
        }
#pragma unroll
        for (int j = 0; j < 4; j++) {
            int rp = wn * 32 + j * 8 + gq;
            bh[j][0] = sXh[rp][tq];
            bh[j][1] = sXh[rp][tq + 4];
            bl[j][0] = sXl[rp][tq];
            bl[j][1] = sXl[rp][tq + 4];
        }
#pragma unroll
        for (int i = 0; i < 2; i++)
#pragma unroll
            for (int j = 0; j < 4; j++) {
                mma16816(acc[i][j], ah[i], bh[j]);
                mma16816(acc[i][j], ah[i], bl[j]);
                mma16816(acc[i][j], al[i], bh[j]);
            }
        if (c + 1 < nch) {
#pragma unroll
            for (int q = 0; q < 8; q++) xr[q] = xr2[q];
        }
    }

#pragma unroll
    for (int i = 0; i < 2; i++) {
#pragma unroll
        for (int half = 0; half < 2; half++) {
            int orow = o0 + wm * 32 + i * 16 + gq + half * 8;
            float gv = g[orow], bv = bi[orow];
            if (MAXPOOL == 0) {
                float* ob = out + (size_t)b * Cout * P + (size_t)orow * P;
#pragma unroll
                for (int j = 0; j < 4; j++) {
                    int pb = p0 + wn * 32 + j * 8 + 2 * tq;
                    float v0 = fmaxf(fmaf(acc[i][j][half * 2], gv, bv), 0.f);
                    float v1 = fmaxf(fmaf(acc[i][j][half * 2 + 1], gv, bv), 0.f);
                    if (pb < P) ob[pb] = v0;
                    if (pb + 1 < P) ob[pb + 1] = v1;
                }
            } else {
                float m = 0.f;
#pragma unroll
                for (int j = 0; j < 4; j++) {
                    m = fmaxf(m, fmaxf(fmaf(acc[i][j][half * 2], gv, bv),
                                       fmaf(acc[i][j][half * 2 + 1], gv, bv)));
                }
                m = fmaxf(m, 0.f);
                m = fmaxf(m, __shfl_xor_sync(0xffffffffu, m, 1));
                m = fmaxf(m, __shfl_xor_sync(0xffffffffu, m, 2));
                if (tq == 0) red[wn][wm * 32 + i * 16 + half * 8 + gq] = m;
            }
        }
    }
    if (MAXPOOL == 1) {
        __syncthreads();
        if (K == 32) {
            int o = tid & 63, grp = tid >> 6;
            if (p0 + grp * 32 < P)
                out[((size_t)b * Cout + o0 + o) * S + (p0 >> 5) + grp] = red[grp][o];
        } else {
            if (tid < 128) {
                int o = tid & 63, grp = tid >> 6;
                if (p0 + grp * 64 < P) {
                    float m = fmaxf(red[2 * grp][o], red[2 * grp + 1][o]);
                    out[((size_t)b * Cout + o0 + o) * S + (p0 >> 6) + grp] = m;
                }
            }
        }
    }
}

// ---------------- dense layer on [B, Cin] vectors (classifier head) ----------------
__global__ void dense_kernel(const float* __restrict__ x, const float* __restrict__ W,
                             const float* __restrict__ g, const float* __restrict__ bi,
                             float* __restrict__ out, int Cin, int Cout, int do_relu) {
    const int b = blockIdx.x;
    const int o = blockIdx.y * 8 + (threadIdx.x >> 5);
    const int lane = threadIdx.x & 31;
    if (o >= Cout) return;
    const float* xb = x + (size_t)b * Cin;
    float acc = 0.f;
    for (int c = lane; c < Cin; c += 32)
        acc = fmaf(W[(size_t)o * Cin + c], xb[c], acc);
#pragma unroll
    for (int off = 16; off; off >>= 1)
        acc += __shfl_xor_sync(0xffffffffu, acc, off);
    if (lane == 0) {
        float v = g ? fmaf(acc, g[o], bi[o]) : (acc + bi[o]);
        if (do_relu) v = fmaxf(v, 0.f);
        out[(size_t)b * Cout + o] = v;
    }
}

// ---------------- launch ----------------
extern "C" void kernel_launch(void* const* d_in, const int* in_sizes, int n_in,
                              void* d_out, int out_size) {
    const float* pc = (const float*)d_in[0];
    const float* saw[3][2];
    const float* sag[3][2];
    const float* sab[3][2];
    for (int sm = 0; sm < 3; sm++)
        for (int l = 0; l < 2; l++) {
            int base = 1 + sm * 6 + l * 3;
            saw[sm][l] = (const float*)d_in[base + 0];
            sag[sm][l] = (const float*)d_in[base + 1];
            sab[sm][l] = (const float*)d_in[base + 2];
        }
    const float* clsw[4];
    const float* clsg[3];
    const float* clsb[4];
    for (int l = 0; l < 3; l++) {
        clsw[l] = (const float*)d_in[19 + l * 3 + 0];
        clsg[l] = (const float*)d_in[19 + l * 3 + 1];
        clsb[l] = (const float*)d_in[19 + l * 3 + 2];
    }
    clsw[3] = (const float*)d_in[28];
    clsb[3] = (const float*)d_in[29];

    float *xyz1, *feat1, *xyz2, *grp1, *h1, *feat2, *xyz3, *grp2, *h2, *feat3;
    float *xyz4, *grp3, *h3, *feat4, *c1, *c2, *c3;
    int *sidx1, *sidx2, *sidx3;
    __nv_bfloat16 *wh, *wl;
    cudaGetSymbolAddress((void**)&xyz1, g_xyz1);
    cudaGetSymbolAddress((void**)&feat1, g_feat1);
    cudaGetSymbolAddress((void**)&sidx1, g_sidx1);
    cudaGetSymbolAddress((void**)&xyz2, g_xyz2);
    cudaGetSymbolAddress((void**)&grp1, g_grp1);
    cudaGetSymbolAddress((void**)&h1, g_h1);
    cudaGetSymbolAddress((void**)&feat2, g_feat2);
    cudaGetSymbolAddress((void**)&sidx2, g_sidx2);
    cudaGetSymbolAddress((void**)&xyz3, g_xyz3);
    cudaGetSymbolAddress((void**)&grp2, g_grp2);
    cudaGetSymbolAddress((void**)&h2, g_h2);
    cudaGetSymbolAddress((void**)&feat3, g_feat3);
    cudaGetSymbolAddress((void**)&sidx3, g_sidx3);
    cudaGetSymbolAddress((void**)&xyz4, g_xyz4);
    cudaGetSymbolAddress((void**)&grp3, g_grp3);
    cudaGetSymbolAddress((void**)&h3, g_h3);
    cudaGetSymbolAddress((void**)&feat4, g_feat4);
    cudaGetSymbolAddress((void**)&c1, g_c1);
    cudaGetSymbolAddress((void**)&c2, g_c2);
    cudaGetSymbolAddress((void**)&c3, g_c3);
    cudaGetSymbolAddress((void**)&wh, g_wh);
    cudaGetSymbolAddress((void**)&wl, g_wl);

    prep_w_kernel<<<(722944 + 255) / 256, 256>>>(saw[0][1], saw[1][0], saw[1][1],
                                                 saw[2][0], saw[2][1]);
    split_kernel<<<(BB * NPTS + 255) / 256, 256>>>(pc, xyz1, feat1);

    // ---- SA1: N=4096 -> S=512, K=32, r=0.1, C: 9 -> 64 -> 128 ----
    fps_kernel<4, true><<<BB, 1024>>>(xyz1, NPTS, 512, sidx1);
    bq_group_kernel<32><<<dim3(512, BB), 256>>>(xyz1, sidx1, feat1, xyz2, grp1,
                                                NPTS, 512, 6, (float)(0.1 * 0.1));
    conv9_kernel<<<dim3(16384 / 256, BB), 256>>>(
        grp1, saw[0][0], sag[0][0], sab[0][0], h1, 16384);
    mma_gemm_kernel<1><<<dim3(16384 / 128, 2, BB), 256>>>(
        h1, wh + WO0, wl + WO0, sag[0][1], sab[0][1], feat2,
        64, 64, 128, 16384, 512, 32);

    // ---- SA2: N=512 -> S=64, K=64, r=0.2, C: 131 -> 128 -> 256 ----
    fps_kernel<1, false><<<BB, 1024>>>(xyz2, 512, 64, sidx2);
    bq_group_kernel<64><<<dim3(64, BB), 256>>>(xyz2, sidx2, feat2, xyz3, grp2,
                                               512, 64, 128, (float)(0.2 * 0.2));
    mma_gemm_kernel<0><<<dim3(4096 / 128, 2, BB), 256>>>(
        grp2, wh + WO1, wl + WO1, sag[1][0], sab[1][0], h2,
        131, 144, 128, 4096, 1, 1);
    mma_gemm_kernel<1><<<dim3(4096 / 128, 4, BB), 256>>>(
        h2, wh + WO2, wl + WO2, sag[1][1], sab[1][1], feat3,
        128, 128, 256, 4096, 64, 64);

    // ---- SA3: N=64 -> S=1, K=64, r=0.4, C: 259 -> 512 -> 1024 ----
    fps_kernel<1, false><<<BB, 1024>>>(xyz3, 64, 1, sidx3);
    bq_group_kernel<64><<<dim3(1, BB), 256>>>(xyz3, sidx3, feat3, xyz4, grp3,
                                              64, 1, 256, (float)(0.4 * 0.4));
    mma_gemm_kernel<0><<<dim3(1, 8, BB), 256>>>(
        grp3, wh + WO3, wl + WO3, sag[2][0], sab[2][0], h3,
        259, 272, 512, 64, 1, 1);
    mma_gemm_kernel<1><<<dim3(1, 16, BB), 256>>>(
        h3, wh + WO4, wl + WO4, sag[2][1], sab[2][1], feat4,
        512, 512, 1024, 64, 1, 64);

    // ---- classifier head on [B, 1024] ----
    dense_kernel<<<dim3(BB, 1024 / 8), 256>>>(feat4, clsw[0], clsg[0], clsb[0], c1, 1024, 1024, 1);
    dense_kernel<<<dim3(BB, 512 / 8), 256>>>(c1, clsw[1], clsg[1], clsb[1], c2, 1024, 512, 1);
    dense_kernel<<<dim3(BB, 128 / 8), 256>>>(c2, clsw[2], clsg[2], clsb[2], c3, 512, 128, 1);
    dense_kernel<<<dim3(BB, (63 + 7) / 8), 256>>>(c3, clsw[3], nullptr, clsb[3],
                                                  (float*)d_out, 128, 63, 0);
}

// round 10
// speedup vs baseline: 1.1510x; 1.0210x over previous
#include <cuda_runtime.h>
#include <cuda_bf16.h>
#include <cstdint>

#define BB 16
#define NPTS 4096

// ---------------- scratch (static device globals; no allocation) ----------------
// xyz buffers are SoA: [B][3][N]
__device__ __align__(16) float g_xyz1[BB * 3 * NPTS];
__device__ __align__(16) float g_feat1[BB * 6 * NPTS];
__device__ __align__(16) int   g_sidx1[BB * 512];
__device__ __align__(16) float g_xyz2[BB * 3 * 512];
__device__ __align__(16) float g_grp1[BB * 9 * 512 * 32];
__device__ __align__(16) float g_h1[BB * 64 * 512 * 32];
__device__ __align__(16) float g_feat2[BB * 128 * 512];
__device__ __align__(16) int   g_sidx2[BB * 64];
__device__ __align__(16) float g_xyz3[BB * 3 * 64];
__device__ __align__(16) float g_grp2[BB * 131 * 64 * 64];
__device__ __align__(16) float g_h2[BB * 128 * 64 * 64];
__device__ __align__(16) float g_feat3[BB * 256 * 64];
__device__ __align__(16) int   g_sidx3[BB * 1];  // zero-init; FPS with npoint=1 is always 0
__device__ __align__(16) float g_xyz4[BB * 3];
__device__ __align__(16) float g_grp3[BB * 259 * 64];
__device__ __align__(16) float g_h3[BB * 512 * 64];
__device__ __align__(16) float g_feat4[BB * 1024];
__device__ __align__(16) float g_c1[BB * 1024];
__device__ __align__(16) float g_c2[BB * 512];
__device__ __align__(16) float g_c3[BB * 128];
// bf16 hi/lo weight planes, [Cout][Cpad] row-major, Cpad = ceil(Cin/16)*16
__device__ __align__(16) __nv_bfloat16 g_wh[722944];
__device__ __align__(16) __nv_bfloat16 g_wl[722944];
#define WO0 0        // SA1-L2: 128 x 64
#define WO1 8192     // SA2-L1: 128 x 144
#define WO2 26624    // SA2-L2: 256 x 128
#define WO3 59392    // SA3-L1: 512 x 272
#define WO4 198656   // SA3-L2: 1024 x 512

// ---------------- helpers ----------------
__device__ __forceinline__ uint32_t smem_u32(const void* p) {
    return (uint32_t)__cvta_generic_to_shared(p);
}
__device__ __forceinline__ void cp16(uint32_t dst, const void* src) {
    asm volatile("cp.async.ca.shared.global [%0], [%1], 16;" :: "r"(dst), "l"(src));
}
__device__ __forceinline__ void cp_commit() {
    asm volatile("cp.async.commit_group;");
}
template <int N>
__device__ __forceinline__ void cp_wait() {
    asm volatile("cp.async.wait_group %0;" :: "n"(N));
}
__device__ __forceinline__ void mma16816(float* c, const uint32_t* a, const uint32_t* b) {
    asm("mma.sync.aligned.m16n8k16.row.col.f32.bf16.bf16.f32 "
        "{%0,%1,%2,%3},{%4,%5,%6,%7},{%8,%9},{%0,%1,%2,%3};"
        : "+f"(c[0]), "+f"(c[1]), "+f"(c[2]), "+f"(c[3])
        : "r"(a[0]), "r"(a[1]), "r"(a[2]), "r"(a[3]), "r"(b[0]), "r"(b[1]));
}
// f32x2 packed ops (per-half IEEE rn — bitwise identical to scalar chain)
__device__ __forceinline__ unsigned long long pk2(float lo, float hi) {
    unsigned long long r;
    asm("mov.b64 %0, {%1, %2};" : "=l"(r) : "f"(lo), "f"(hi));
    return r;
}
__device__ __forceinline__ void upk2(float& lo, float& hi, unsigned long long v) {
    asm("mov.b64 {%0, %1}, %2;" : "=f"(lo), "=f"(hi) : "l"(v));
}
__device__ __forceinline__ unsigned long long add2(unsigned long long a,
                                                   unsigned long long b) {
    unsigned long long r;
    asm("add.rn.f32x2 %0, %1, %2;" : "=l"(r) : "l"(a), "l"(b));
    return r;
}
__device__ __forceinline__ unsigned long long mul2(unsigned long long a,
                                                   unsigned long long b) {
    unsigned long long r;
    asm("mul.rn.f32x2 %0, %1, %2;" : "=l"(r) : "l"(a), "l"(b));
    return r;
}

// ---------------- merged prep (weights->bf16 hi/lo) + split (pc->SoA) -------------
#define PREP_BLOCKS 2824  // 722944 / 256
__global__ void prep_split_kernel(const float* __restrict__ w0, const float* __restrict__ w1,
                                  const float* __restrict__ w2, const float* __restrict__ w3,
                                  const float* __restrict__ w4, const float* __restrict__ pc,
                                  float* __restrict__ xyz, float* __restrict__ feat) {
    if (blockIdx.x < PREP_BLOCKS) {
        int i = blockIdx.x * 256 + threadIdx.x;
        const float* W;
        int Cin, Cpad;
        size_t off;
        if (i < 8192)        { W = w0; Cin = 64;  Cpad = 64;  off = WO0; }
        else if (i < 26624)  { W = w1; Cin = 131; Cpad = 144; off = WO1; i -= 8192; }
        else if (i < 59392)  { W = w2; Cin = 128; Cpad = 128; off = WO2; i -= 26624; }
        else if (i < 198656) { W = w3; Cin = 259; Cpad = 272; off = WO3; i -= 59392; }
        else if (i < 722944) { W = w4; Cin = 512; Cpad = 512; off = WO4; i -= 198656; }
        else return;
        int o = i / Cpad, c = i - o * Cpad;
        float v = (c < Cin) ? W[(size_t)o * Cin + c] : 0.f;
        __nv_bfloat16 h = __float2bfloat16(v);
        float lo = v - __bfloat162float(h);
        g_wh[off + i] = h;
        g_wl[off + i] = __float2bfloat16(lo);
    } else {
        int idx = (blockIdx.x - PREP_BLOCKS) * 256 + threadIdx.x;
        if (idx >= BB * NPTS) return;
        int b = idx / NPTS, n = idx % NPTS;
        const float* p = pc + (size_t)idx * 9;
#pragma unroll
        for (int k = 0; k < 3; k++)
            xyz[((size_t)b * 3 + k) * NPTS + n] = p[k];
#pragma unroll
        for (int c = 0; c < 6; c++)
            feat[((size_t)b * 6 + c) * NPTS + n] = p[3 + c];
    }
}

// ---------------- FPS: SoA input, two-level REDUX, optional f32x2 -----------------
// xyz: [B][3][N] SoA. PACKED requires N == 4*blockDim (no bounds checks).
template <int ITEMS, bool PACKED>
__global__ void fps_kernel(const float* __restrict__ xyz, int N, int npoint,
                           int* __restrict__ out) {
    const int b = blockIdx.x;
    const float* X = xyz + (size_t)b * 3 * N;
    const float* Y = X + N;
    const float* Z = X + 2 * N;
    const int tid = threadIdx.x;
    const int nw = blockDim.x >> 5;

    __shared__ int s_far;
    __shared__ unsigned sv[32];
    __shared__ unsigned si[32];
    if (tid == 0) s_far = 0;

    unsigned long long lx2[(ITEMS + 1) / 2], ly2[(ITEMS + 1) / 2],
        lz2[(ITEMS + 1) / 2], ld2[(ITEMS + 1) / 2];
    float lx[ITEMS], ly[ITEMS], lz[ITEMS], ld[ITEMS];

    if (PACKED) {
#pragma unroll
        for (int p = 0; p < ITEMS / 2; p++) {
            int n0 = tid + (2 * p) * 1024, n1 = tid + (2 * p + 1) * 1024;
            lx2[p] = pk2(X[n0], X[n1]);
            ly2[p] = pk2(Y[n0], Y[n1]);
            lz2[p] = pk2(Z[n0], Z[n1]);
            ld2[p] = pk2(1e10f, 1e10f);
        }
    } else {
#pragma unroll
        for (int i = 0; i < ITEMS; i++) {
            int n = tid + i * 1024;
            if (n < N) {
                lx[i] = X[n];
                ly[i] = Y[n];
                lz[i] = Z[n];
                ld[i] = 1e10f;
            } else {
                ld[i] = -1.0f;
            }
        }
    }
    __syncthreads();

    for (int it = 0; it < npoint; it++) {
        int far = s_far;
        if (tid == 0) out[b * npoint + it] = far;
        float cx = X[far], cy = Y[far], cz = Z[far];

        float bv = -1.0f;
        int bi = 0;
        if (PACKED) {
            unsigned long long ncx = pk2(-cx, -cx);
            unsigned long long ncy = pk2(-cy, -cy);
            unsigned long long ncz = pk2(-cz, -cz);
#pragma unroll
            for (int p = 0; p < ITEMS / 2; p++) {
                unsigned long long dx = add2(lx2[p], ncx);
                unsigned long long dy = add2(ly2[p], ncy);
                unsigned long long dz = add2(lz2[p], ncz);
                unsigned long long d =
                    add2(add2(mul2(dx, dx), mul2(dy, dy)), mul2(dz, dz));
                float d0, d1, l0, l1;
                upk2(d0, d1, d);
                upk2(l0, l1, ld2[p]);
                float n0 = fminf(l0, d0), n1 = fminf(l1, d1);
                ld2[p] = pk2(n0, n1);
                if (n0 > bv) { bv = n0; bi = tid + (2 * p) * 1024; }
                if (n1 > bv) { bv = n1; bi = tid + (2 * p + 1) * 1024; }
            }
        } else {
#pragma unroll
            for (int i = 0; i < ITEMS; i++) {
                int n = tid + i * 1024;
                if (n < N) {
                    float dx = __fsub_rn(lx[i], cx);
                    float dy = __fsub_rn(ly[i], cy);
                    float dz = __fsub_rn(lz[i], cz);
                    float d = __fadd_rn(__fadd_rn(__fmul_rn(dx, dx), __fmul_rn(dy, dy)),
                                        __fmul_rn(dz, dz));
                    float nd = fminf(ld[i], d);
                    ld[i] = nd;
                    if (nd > bv) { bv = nd; bi = n; }
                }
            }
        }
        // dists nonneg -> float bits order-preserving; tie-break = smallest index
        unsigned ub = (PACKED || tid < N) ? __float_as_uint(bv) : 0u;
        unsigned wmax = __reduce_max_sync(0xffffffffu, ub);
        unsigned uidx = ((PACKED || tid < N) && ub == wmax) ? (unsigned)bi : 0xffffffffu;
        unsigned wimin = __reduce_min_sync(0xffffffffu, uidx);
        if ((tid & 31) == 0) { sv[tid >> 5] = wmax; si[tid >> 5] = wimin; }
        __syncthreads();
        if (tid < 32) {
            unsigned v2 = (tid < nw) ? sv[tid] : 0u;
            unsigned i2 = (tid < nw) ? si[tid] : 0xffffffffu;
            unsigned m2 = __reduce_max_sync(0xffffffffu, v2);
            unsigned ii = (v2 == m2) ? i2 : 0xffffffffu;
            unsigned fi = __reduce_min_sync(0xffffffffu, ii);
            if (tid == 0) s_far = (int)fi;
        }
        __syncthreads();
    }
}

// ---------------- ball query + gather/group: CS centers per block ----------------
// Phase A: all warps ballot all N points against CS centers (points loaded once).
// Phase B: warp w prefix-sums group popcounts of center w.
// Phase C: warp w extracts first-K indices of center w; pad with rank-0 hit or 0.
// Semantics identical to JAX first-K-in-index-order with pad-by-first.
template <int K, int CS>
__global__ void bq_group_kernel(const float* __restrict__ xyz, const int* __restrict__ sidx,
                                const float* __restrict__ feats,
                                float* __restrict__ new_xyz, float* __restrict__ grp,
                                int N, int S, int Cf, float r2) {
    const int b = blockIdx.y, s0 = blockIdx.x * CS;
    const float* X = xyz + (size_t)b * 3 * N;
    const float* Y = X + N;
    const float* Z = X + 2 * N;
    const int tid = threadIdx.x;
    const int w = tid >> 5, l = tid & 31;

    __shared__ float scx[CS], scy[CS], scz[CS];
    __shared__ unsigned smask[CS][128];
    __shared__ int sbase[CS][128];
    __shared__ int stot[CS];
    __shared__ int sIdx[CS][K];

    if (tid < CS) {
        int ci = sidx[b * S + s0 + tid];
        float x = X[ci], y = Y[ci], z = Z[ci];
        scx[tid] = x;
        scy[tid] = y;
        scz[tid] = z;
        new_xyz[((size_t)b * 3 + 0) * S + s0 + tid] = x;
        new_xyz[((size_t)b * 3 + 1) * S + s0 + tid] = y;
        new_xyz[((size_t)b * 3 + 2) * S + s0 + tid] = z;
    }
    __syncthreads();

    float ccx[CS], ccy[CS], ccz[CS];
#pragma unroll
    for (int cs = 0; cs < CS; cs++) {
        ccx[cs] = scx[cs];
        ccy[cs] = scy[cs];
        ccz[cs] = scz[cs];
    }

    const int NG = (N + 31) >> 5;
    const int gpw = (NG + 7) >> 3;

    // Phase A
    for (int gi = 0; gi < gpw; gi++) {
        int g = w * gpw + gi;
        if (g < NG) {
            int j = (g << 5) + l;
            bool valid = j < N;
            float x = valid ? X[j] : 0.f;
            float y = valid ? Y[j] : 0.f;
            float z = valid ? Z[j] : 0.f;
#pragma unroll
            for (int cs = 0; cs < CS; cs++) {
                bool pred = false;
                if (valid) {
                    float dx = __fsub_rn(ccx[cs], x);
                    float dy = __fsub_rn(ccy[cs], y);
                    float dz = __fsub_rn(ccz[cs], z);
                    float d2 = __fadd_rn(__fadd_rn(__fmul_rn(dx, dx), __fmul_rn(dy, dy)),
                                         __fmul_rn(dz, dz));
                    pred = (d2 < r2);
                }
                unsigned m = __ballot_sync(0xffffffffu, pred);
                if (l == 0) smask[cs][g] = m;
            }
        }
    }
    __syncthreads();

    // Phase B: warp w handles center w (CS <= 8)
    if (w < CS) {
        const int gpl = (NG + 31) >> 5;
        int cnt = 0;
#pragma unroll 4
        for (int q = 0; q < gpl; q++) {
            int g = l * gpl + q;
            if (g < NG) cnt += __popc(smask[w][g]);
        }
        int inc = cnt;
#pragma unroll
        for (int off = 1; off < 32; off <<= 1) {
            int v = __shfl_up_sync(0xffffffffu, inc, off);
            if (l >= off) inc += v;
        }
        int total = __shfl_sync(0xffffffffu, inc, 31);
        int run = inc - cnt;
#pragma unroll 4
        for (int q = 0; q < gpl; q++) {
            int g = l * gpl + q;
            if (g < NG) {
                sbase[w][g] = run;
                run += __popc(smask[w][g]);
            }
        }
        if (l == 0) stot[w] = total;

        // Phase C: extract first-K for center w (base monotonic -> uniform break)
        for (int g = 0; g < NG; g++) {
            unsigned m = smask[w][g];
            if (m == 0u) continue;
            int base = sbase[w][g];
            if (base >= K) break;
            if (m & (1u << l)) {
                int pos = base + __popc(m & ((1u << l) - 1u));
                if (pos < K) sIdx[w][pos] = (g << 5) + l;
            }
        }
        __syncwarp();
        int fillv = (total > 0) ? sIdx[w][0] : 0;
        for (int k = total + l; k < K; k += 32) sIdx[w][k] = fillv;
    }
    __syncthreads();

    // gather
    const int C = 3 + Cf;
    const size_t SK = (size_t)S * K;
#pragma unroll 1
    for (int cs = 0; cs < CS; cs++) {
        const int s = s0 + cs;
        const float cx = ccx[cs], cy = ccy[cs], cz = ccz[cs];
        const size_t pbase = (size_t)s * K;
        for (int e = tid; e < C * K; e += 256) {
            int ch = e / K, k = e - ch * K;  // K compile-time -> shifts
            int j = sIdx[cs][k];
            float v;
            if (ch == 0)      v = __fsub_rn(X[j], cx);
            else if (ch == 1) v = __fsub_rn(Y[j], cy);
            else if (ch == 2) v = __fsub_rn(Z[j], cz);
            else              v = feats[((size_t)b * Cf + (ch - 3)) * N + j];
            grp[((size_t)b * C + ch) * SK + pbase + k] = v;
        }
    }
}

// ---------------- SA1 layer1: 9 -> 64 streaming conv + BN + ReLU ----------------
__global__ void conv9_kernel(const float* __restrict__ x, const float* __restrict__ W,
                             const float* __restrict__ g, const float* __restrict__ bi,
                             float* __restrict__ out, int P) {
    __shared__ float ws[64 * 9];
    __shared__ float gs[64], bs[64];
    const int tid = threadIdx.x;
    if (tid < 64) { gs[tid] = g[tid]; bs[tid] = bi[tid]; }
    for (int e = tid; e < 576; e += 256) ws[e] = W[e];
    __syncthreads();

    const int b = blockIdx.y;
    const int p = blockIdx.x * 256 + tid;
    const float* xb = x + (size_t)b * 9 * P;
    float xv[9];
#pragma unroll
    for (int c = 0; c < 9; c++) xv[c] = xb[(size_t)c * P + p];
    float* ob = out + (size_t)b * 64 * P;
#pragma unroll 8
    for (int o = 0; o < 64; o++) {
        float a = 0.f;
#pragma unroll
        for (int c = 0; c < 9; c++) a = fmaf(ws[o * 9 + c], xv[c], a);
        ob[(size_t)o * P + p] = fmaxf(fmaf(a, gs[o], bs[o]), 0.f);
    }
}

// ---------------- bf16 split-MMA GEMM: 64o x 128p block tile, K-chunk 16 -----------
template <int MAXPOOL>
__global__ __launch_bounds__(256, 2) void mma_gemm_kernel(
    const float* __restrict__ x, const __nv_bfloat16* __restrict__ Wh,
    const __nv_bfloat16* __restrict__ Wl, const float* __restrict__ g,
    const float* __restrict__ bi, float* __restrict__ out,
    int Cin, int Cpad, int Cout, int P, int S, int K) {
    __shared__ uint32_t sWh[2][64][12], sWl[2][64][12];
    __shared__ uint32_t sXh[128][12], sXl[128][12];
    __shared__ float red[4][64];

    const int b = blockIdx.z;
    const int o0 = blockIdx.y * 64;
    const int p0 = blockIdx.x * 128;
    const int tid = threadIdx.x;
    const int w = tid >> 5, l = tid & 31;
    const int gq = l >> 2, tq = l & 3;
    const int wm = w & 1, wn = w >> 1;

    const float* xb = x + (size_t)b * Cin * P;
    const int nch = (Cin + 15) >> 4;

    float acc[2][4][4];
#pragma unroll
    for (int i = 0; i < 2; i++)
#pragma unroll
        for (int j = 0; j < 4; j++)
#pragma unroll
            for (int r = 0; r < 4; r++) acc[i][j][r] = 0.f;

    auto stage_w = [&](int c0, int buf) {
        int which = tid & 1, r = (tid >> 1) & 63, half = (tid >> 7) & 1;
        const __nv_bfloat16* src =
            (which ? Wl : Wh) + (size_t)(o0 + r) * Cpad + c0 + half * 8;
        uint32_t dst = smem_u32(which ? &sWl[buf][r][half * 4] : &sWh[buf][r][half * 4]);
        cp16(dst, src);
    };
    const int xp = tid & 127;
    const int xch = (tid >> 7) * 8;
    auto load_x = [&](int c0, float xr[8]) {
        bool pv = (p0 + xp) < P;
#pragma unroll
        for (int q = 0; q < 8; q++) {
            int cc = c0 + xch + q;
            xr[q] = (pv && cc < Cin) ? xb[(size_t)cc * P + p0 + xp] : 0.f;
        }
    };
    auto store_x = [&](const float xr[8]) {
        uint32_t hq[4], lq[4];
#pragma unroll
        for (int k = 0; k < 4; k++) {
            float a = xr[2 * k], c = xr[2 * k + 1];
            __nv_bfloat16 ah = __float2bfloat16(a), ch = __float2bfloat16(c);
            float al = a - __bfloat162float(ah), cl = c - __bfloat162float(ch);
            hq[k] = (uint32_t)__bfloat16_as_ushort(ah) |
                    ((uint32_t)__bfloat16_as_ushort(ch) << 16);
            lq[k] = (uint32_t)__bfloat16_as_ushort(__float2bfloat16(al)) |
                    ((uint32_t)__bfloat16_as_ushort(__float2bfloat16(cl)) << 16);
        }
        *(uint4*)&sXh[xp][(xch >> 1)] = make_uint4(hq[0], hq[1], hq[2], hq[3]);
        *(uint4*)&sXl[xp][(xch >> 1)] = make_uint4(lq[0], lq[1], lq[2], lq[3]);
    };

    float xr[8], xr2[8];
    load_x(0, xr);
    stage_w(0, 0);
    cp_commit();

    for (int c = 0; c < nch; c++) {
        __syncthreads();
        store_x(xr);
        if (c + 1 < nch) {
            load_x((c + 1) * 16, xr2);
            stage_w((c + 1) * 16, (c + 1) & 1);
            cp_commit();
            cp_wait<1>();
        } else {
            cp_wait<0>();
        }
        __syncthreads();

        const uint32_t(*wh)[12] = sWh[c & 1];
        const uint32_t(*wl)[12] = sWl[c & 1];
        uint32_t ah[2][4], al[2][4], bh[4][2], bl[4][2];
#pragma unroll
        for (int i = 0; i < 2; i++) {
            int ro = wm * 32 + i * 16;
            ah[i][0] = wh[ro + gq][tq];
            ah[i][1] = wh[ro + gq + 8][tq];
            ah[i][2] = wh[ro + gq][tq + 4];
            ah[i][3] = wh[ro + gq + 8][tq + 4];
            al[i][0] = wl[ro + gq][tq];
            al[i][1] = wl[ro + gq + 8][tq];
            al[i][2] = wl[ro + gq][tq + 4];
            al[i][3] = wl[ro + gq + 8][tq + 4];
        }
#pragma unroll
        for (int j = 0; j < 4; j++) {
            int rp = wn * 32 + j * 8 + gq;
            bh[j][0] = sXh[rp][tq];
            bh[j][1] = sXh[rp][tq + 4];
            bl[j][0] = sXl[rp][tq];
            bl[j][1] = sXl[rp][tq + 4];
        }
#pragma unroll
        for (int i = 0; i < 2; i++)
#pragma unroll
            for (int j = 0; j < 4; j++) {
                mma16816(acc[i][j], ah[i], bh[j]);
                mma16816(acc[i][j], ah[i], bl[j]);
                mma16816(acc[i][j], al[i], bh[j]);
            }
        if (c + 1 < nch) {
#pragma unroll
            for (int q = 0; q < 8; q++) xr[q] = xr2[q];
        }
    }

#pragma unroll
    for (int i = 0; i < 2; i++) {
#pragma unroll
        for (int half = 0; half < 2; half++) {
            int orow = o0 + wm * 32 + i * 16 + gq + half * 8;
            float gv = g[orow], bv = bi[orow];
            if (MAXPOOL == 0) {
                float* ob = out + (size_t)b * Cout * P + (size_t)orow * P;
#pragma unroll
                for (int j = 0; j < 4; j++) {
                    int pb = p0 + wn * 32 + j * 8 + 2 * tq;
                    float v0 = fmaxf(fmaf(acc[i][j][half * 2], gv, bv), 0.f);
                    float v1 = fmaxf(fmaf(acc[i][j][half * 2 + 1], gv, bv), 0.f);
                    if (pb < P) ob[pb] = v0;
                    if (pb + 1 < P) ob[pb + 1] = v1;
                }
            } else {
                float m = 0.f;
#pragma unroll
                for (int j = 0; j < 4; j++) {
                    m = fmaxf(m, fmaxf(fmaf(acc[i][j][half * 2], gv, bv),
                                       fmaf(acc[i][j][half * 2 + 1], gv, bv)));
                }
                m = fmaxf(m, 0.f);
                m = fmaxf(m, __shfl_xor_sync(0xffffffffu, m, 1));
                m = fmaxf(m, __shfl_xor_sync(0xffffffffu, m, 2));
                if (tq == 0) red[wn][wm * 32 + i * 16 + half * 8 + gq] = m;
            }
        }
    }
    if (MAXPOOL == 1) {
        __syncthreads();
        if (K == 32) {
            int o = tid & 63, grp = tid >> 6;
            if (p0 + grp * 32 < P)
                out[((size_t)b * Cout + o0 + o) * S + (p0 >> 5) + grp] = red[grp][o];
        } else {
            if (tid < 128) {
                int o = tid & 63, grp = tid >> 6;
                if (p0 + grp * 64 < P) {
                    float m = fmaxf(red[2 * grp][o], red[2 * grp + 1][o]);
                    out[((size_t)b * Cout + o0 + o) * S + (p0 >> 6) + grp] = m;
                }
            }
        }
    }
}

// ---------------- dense layer on [B, Cin] vectors (classifier head) ----------------
__global__ void dense_kernel(const float* __restrict__ x, const float* __restrict__ W,
                             const float* __restrict__ g, const float* __restrict__ bi,
                             float* __restrict__ out, int Cin, int Cout, int do_relu) {
    const int b = blockIdx.x;
    const int o = blockIdx.y * 8 + (threadIdx.x >> 5);
    const int lane = threadIdx.x & 31;
    if (o >= Cout) return;
    const float* xb = x + (size_t)b * Cin;
    float acc = 0.f;
    for (int c = lane; c < Cin; c += 32)
        acc = fmaf(W[(size_t)o * Cin + c], xb[c], acc);
#pragma unroll
    for (int off = 16; off; off >>= 1)
        acc += __shfl_xor_sync(0xffffffffu, acc, off);
    if (lane == 0) {
        float v = g ? fmaf(acc, g[o], bi[o]) : (acc + bi[o]);
        if (do_relu) v = fmaxf(v, 0.f);
        out[(size_t)b * Cout + o] = v;
    }
}

// ---------------- launch ----------------
extern "C" void kernel_launch(void* const* d_in, const int* in_sizes, int n_in,
                              void* d_out, int out_size) {
    const float* pc = (const float*)d_in[0];
    const float* saw[3][2];
    const float* sag[3][2];
    const float* sab[3][2];
    for (int sm = 0; sm < 3; sm++)
        for (int l = 0; l < 2; l++) {
            int base = 1 + sm * 6 + l * 3;
            saw[sm][l] = (const float*)d_in[base + 0];
            sag[sm][l] = (const float*)d_in[base + 1];
            sab[sm][l] = (const float*)d_in[base + 2];
        }
    const float* clsw[4];
    const float* clsg[3];
    const float* clsb[4];
    for (int l = 0; l < 3; l++) {
        clsw[l] = (const float*)d_in[19 + l * 3 + 0];
        clsg[l] = (const float*)d_in[19 + l * 3 + 1];
        clsb[l] = (const float*)d_in[19 + l * 3 + 2];
    }
    clsw[3] = (const float*)d_in[28];
    clsb[3] = (const float*)d_in[29];

    float *xyz1, *feat1, *xyz2, *grp1, *h1, *feat2, *xyz3, *grp2, *h2, *feat3;
    float *xyz4, *grp3, *h3, *feat4, *c1, *c2, *c3;
    int *sidx1, *sidx2, *sidx3;
    __nv_bfloat16 *wh, *wl;
    cudaGetSymbolAddress((void**)&xyz1, g_xyz1);
    cudaGetSymbolAddress((void**)&feat1, g_feat1);
    cudaGetSymbolAddress((void**)&sidx1, g_sidx1);
    cudaGetSymbolAddress((void**)&xyz2, g_xyz2);
    cudaGetSymbolAddress((void**)&grp1, g_grp1);
    cudaGetSymbolAddress((void**)&h1, g_h1);
    cudaGetSymbolAddress((void**)&feat2, g_feat2);
    cudaGetSymbolAddress((void**)&sidx2, g_sidx2);
    cudaGetSymbolAddress((void**)&xyz3, g_xyz3);
    cudaGetSymbolAddress((void**)&grp2, g_grp2);
    cudaGetSymbolAddress((void**)&h2, g_h2);
    cudaGetSymbolAddress((void**)&feat3, g_feat3);
    cudaGetSymbolAddress((void**)&sidx3, g_sidx3);
    cudaGetSymbolAddress((void**)&xyz4, g_xyz4);
    cudaGetSymbolAddress((void**)&grp3, g_grp3);
    cudaGetSymbolAddress((void**)&h3, g_h3);
    cudaGetSymbolAddress((void**)&feat4, g_feat4);
    cudaGetSymbolAddress((void**)&c1, g_c1);
    cudaGetSymbolAddress((void**)&c2, g_c2);
    cudaGetSymbolAddress((void**)&c3, g_c3);
    cudaGetSymbolAddress((void**)&wh, g_wh);
    cudaGetSymbolAddress((void**)&wl, g_wl);

    // merged weight-prep + split (split blocks: 65536/256 = 256)
    prep_split_kernel<<<PREP_BLOCKS + 256, 256>>>(saw[0][1], saw[1][0], saw[1][1],
                                                  saw[2][0], saw[2][1], pc, xyz1, feat1);

    // ---- SA1: N=4096 -> S=512, K=32, r=0.1, C: 9 -> 64 -> 128 ----
    fps_kernel<4, true><<<BB, 1024>>>(xyz1, NPTS, 512, sidx1);
    bq_group_kernel<32, 8><<<dim3(512 / 8, BB), 256>>>(xyz1, sidx1, feat1, xyz2, grp1,
                                                       NPTS, 512, 6, (float)(0.1 * 0.1));
    conv9_kernel<<<dim3(16384 / 256, BB), 256>>>(
        grp1, saw[0][0], sag[0][0], sab[0][0], h1, 16384);
    mma_gemm_kernel<1><<<dim3(16384 / 128, 2, BB), 256>>>(
        h1, wh + WO0, wl + WO0, sag[0][1], sab[0][1], feat2,
        64, 64, 128, 16384, 512, 32);

    // ---- SA2: N=512 -> S=64, K=64, r=0.2, C: 131 -> 128 -> 256 ----
    fps_kernel<1, false><<<BB, 512>>>(xyz2, 512, 64, sidx2);
    bq_group_kernel<64, 8><<<dim3(64 / 8, BB), 256>>>(xyz2, sidx2, feat2, xyz3, grp2,
                                                      512, 64, 128, (float)(0.2 * 0.2));
    mma_gemm_kernel<0><<<dim3(4096 / 128, 2, BB), 256>>>(
        grp2, wh + WO1, wl + WO1, sag[1][0], sab[1][0], h2,
        131, 144, 128, 4096, 1, 1);
    mma_gemm_kernel<1><<<dim3(4096 / 128, 4, BB), 256>>>(
        h2, wh + WO2, wl + WO2, sag[1][1], sab[1][1], feat3,
        128, 128, 256, 4096, 64, 64);

    // ---- SA3: N=64 -> S=1, K=64, r=0.4, C: 259 -> 512 -> 1024 ----
    // fps with npoint=1 always yields index 0; g_sidx3 is zero-initialized and
    // never written -> skip the FPS launch entirely.
    bq_group_kernel<64, 1><<<dim3(1, BB), 256>>>(xyz3, sidx3, feat3, xyz4, grp3,
                                                 64, 1, 256, (float)(0.4 * 0.4));
    mma_gemm_kernel<0><<<dim3(1, 8, BB), 256>>>(
        grp3, wh + WO3, wl + WO3, sag[2][0], sab[2][0], h3,
        259, 272, 512, 64, 1, 1);
    mma_gemm_kernel<1><<<dim3(1, 16, BB), 256>>>(
        h3, wh + WO4, wl + WO4, sag[2][1], sab[2][1], feat4,
        512, 512, 1024, 64, 1, 64);

    // ---- classifier head on [B, 1024] ----
    dense_kernel<<<dim3(BB, 1024 / 8), 256>>>(feat4, clsw[0], clsg[0], clsb[0], c1, 1024, 1024, 1);
    dense_kernel<<<dim3(BB, 512 / 8), 256>>>(c1, clsw[1], clsg[1], clsb[1], c2, 1024, 512, 1);
    dense_kernel<<<dim3(BB, 128 / 8), 256>>>(c2, clsw[2], clsg[2], clsb[2], c3, 512, 128, 1);
    dense_kernel<<<dim3(BB, (63 + 7) / 8), 256>>>(c3, clsw[3], nullptr, clsb[3],
                                                  (float*)d_out, 128, 63, 0);
}